// round 3
// baseline (speedup 1.0000x reference)
#include <cuda_runtime.h>
#include <cuda_bf16.h>
#include <cstdint>

// Problem constants (match reference)
#define N_NODES 100000
#define N_EDGES 3200000
#define D_FEAT  64

// ---------------- scratch (static device globals; no allocation) -------------
__device__ float g_hA[(size_t)N_NODES * D_FEAT];   // 25.6 MB
__device__ float g_hB[(size_t)N_NODES * D_FEAT];   // 25.6 MB
__device__ int   g_deg[N_NODES];
__device__ int   g_rowptr[N_NODES + 1];
__device__ int   g_cursor[N_NODES];
__device__ int   g_src_csr[N_EDGES];               // 12.8 MB
__device__ float g_w_csr[N_EDGES];                 // 12.8 MB

// ---------------- CSR build --------------------------------------------------
__global__ void zero_deg_kernel() {
    int i = blockIdx.x * blockDim.x + threadIdx.x;
    if (i < N_NODES) g_deg[i] = 0;
}

__global__ void hist_kernel(const int* __restrict__ dst) {
    int e = blockIdx.x * blockDim.x + threadIdx.x;
    if (e < N_EDGES) atomicAdd(&g_deg[dst[e]], 1);
}

// Single-CTA exclusive scan over g_deg -> g_rowptr (N=100k, 1024 threads,
// ~98 sequential elements per thread + Hillis-Steele over partials).
__global__ void scan_kernel() {
    const int CH = (N_NODES + 1023) / 1024;   // 98
    __shared__ int sh[1024];
    int t = threadIdx.x;
    int begin = t * CH;
    int endv  = begin + CH; if (endv > N_NODES) endv = N_NODES;
    int sum = 0;
    for (int i = begin; i < endv; i++) sum += g_deg[i];
    sh[t] = sum;
    __syncthreads();
    // inclusive Hillis-Steele scan of 1024 partials
    for (int off = 1; off < 1024; off <<= 1) {
        int v = (t >= off) ? sh[t - off] : 0;
        __syncthreads();
        sh[t] += v;
        __syncthreads();
    }
    int excl = (t == 0) ? 0 : sh[t - 1];
    for (int i = begin; i < endv; i++) {
        g_rowptr[i] = excl;
        excl += g_deg[i];
    }
    if (t == 1023) g_rowptr[N_NODES] = sh[1023];   // == N_EDGES
}

__global__ void init_cursor_kernel() {
    int i = blockIdx.x * blockDim.x + threadIdx.x;
    if (i < N_NODES) g_cursor[i] = g_rowptr[i];
}

__global__ void scatter_kernel(const int* __restrict__ src,
                               const int* __restrict__ dst,
                               const float* __restrict__ w) {
    int e = blockIdx.x * blockDim.x + threadIdx.x;
    if (e < N_EDGES) {
        int d   = dst[e];
        int pos = atomicAdd(&g_cursor[d], 1);
        g_src_csr[pos] = src[e];
        g_w_csr[pos]   = w[e];
    }
}

// ---------------- SpMM hop: warp-per-node, register accumulators -------------
// Each warp owns one output row (64 floats -> float2 per lane). Edge list for
// the row is loaded coalesced in chunks of 32 (one per lane), broadcast via
// shuffles; feature gathers are one LDG.64 per lane per edge (256B per edge,
// two full 128B lines, perfectly coalesced).
__global__ void __launch_bounds__(256, 8)
spmm_kernel(const float* __restrict__ hin, float* __restrict__ hout) {
    int warp = blockIdx.x * (blockDim.x >> 5) + (threadIdx.x >> 5);
    int lane = threadIdx.x & 31;
    if (warp >= N_NODES) return;

    int beg = g_rowptr[warp];
    int end = g_rowptr[warp + 1];

    float2 acc = make_float2(0.0f, 0.0f);

    const float2* hin2 = (const float2*)hin;

    int base = beg;
    // full chunks of 32 edges: fully unrolled inner loop for MLP
    for (; base + 32 <= end; base += 32) {
        int   s  = g_src_csr[base + lane];
        float wt = g_w_csr[base + lane];
        #pragma unroll
        for (int j = 0; j < 32; j++) {
            int   ss = __shfl_sync(0xffffffffu, s,  j);
            float ww = __shfl_sync(0xffffffffu, wt, j);
            float2 v = __ldg(hin2 + (size_t)ss * (D_FEAT / 2) + lane);
            acc.x = fmaf(ww, v.x, acc.x);
            acc.y = fmaf(ww, v.y, acc.y);
        }
    }
    // tail
    if (base < end) {
        int rem  = end - base;
        int   s  = 0; float wt = 0.0f;
        if (lane < rem) { s = g_src_csr[base + lane]; wt = g_w_csr[base + lane]; }
        for (int j = 0; j < rem; j++) {
            int   ss = __shfl_sync(0xffffffffu, s,  j);
            float ww = __shfl_sync(0xffffffffu, wt, j);
            float2 v = __ldg(hin2 + (size_t)ss * (D_FEAT / 2) + lane);
            acc.x = fmaf(ww, v.x, acc.x);
            acc.y = fmaf(ww, v.y, acc.y);
        }
    }

    float2* orow = (float2*)(hout + (size_t)warp * D_FEAT);
    orow[lane] = acc;
}

// ---------------- launch -----------------------------------------------------
extern "C" void kernel_launch(void* const* d_in, const int* in_sizes, int n_in,
                              void* d_out, int out_size) {
    const float* x  = (const float*)d_in[0];   // [N, 64]
    const float* ew = (const float*)d_in[1];   // [E]
    const int*   src = (const int*)d_in[2];    // [E]
    const int*   dst = (const int*)d_in[3];    // [E]
    float* out = (float*)d_out;                // [N, 64]

    const int TB = 256;
    const int gN = (N_NODES + TB - 1) / TB;
    const int gE = (N_EDGES + TB - 1) / TB;

    // CSR build
    zero_deg_kernel<<<gN, TB>>>();
    hist_kernel<<<gE, TB>>>(dst);
    scan_kernel<<<1, 1024>>>();
    init_cursor_kernel<<<gN, TB>>>();
    scatter_kernel<<<gE, TB>>>(src, dst, ew);

    // 3 hops, warp per node (8 warps per block)
    const int warpsPerBlock = TB / 32;
    const int gS = (N_NODES + warpsPerBlock - 1) / warpsPerBlock;

    float* hA = nullptr, * hB = nullptr;
    cudaGetSymbolAddress((void**)&hA, g_hA);
    cudaGetSymbolAddress((void**)&hB, g_hB);

    spmm_kernel<<<gS, TB>>>(x,  hA);
    spmm_kernel<<<gS, TB>>>(hA, hB);
    spmm_kernel<<<gS, TB>>>(hB, out);
}

// round 12
// speedup vs baseline: 1.5880x; 1.5880x over previous
#include <cuda_runtime.h>
#include <cuda_fp16.h>
#include <cstdint>

// Problem constants (match reference)
#define N_NODES 100000
#define N_EDGES 3200000
#define D_FEAT  64

#define SCAN_B   1024
#define SCAN_NBLK ((N_NODES + SCAN_B - 1) / SCAN_B)   // 98

// ---------------- scratch (static device globals; no allocation) -------------
__device__ __half2 g_xh[(size_t)N_NODES * 32];   // x in fp16       (12.8 MB)
__device__ __half2 g_h1[(size_t)N_NODES * 32];   // hop1 out fp16   (12.8 MB)
__device__ __half2 g_h2[(size_t)N_NODES * 32];   // hop2 out fp16   (12.8 MB)
__device__ int   g_deg[N_NODES];
__device__ int   g_excl[N_NODES];                // block-local exclusive scan
__device__ int   g_bsum[SCAN_NBLK];
__device__ int   g_boff[SCAN_NBLK];
__device__ int   g_rowptr[N_NODES + 1];
__device__ int   g_cursor[N_NODES];
__device__ int2  g_csr[N_EDGES];                 // {src, w_bits}   (25.6 MB)

// ---------------- CSR build --------------------------------------------------
__global__ void hist_kernel(const int* __restrict__ dst) {
    int e = blockIdx.x * blockDim.x + threadIdx.x;
    if (e < N_EDGES) atomicAdd(&g_deg[dst[e]], 1);
}

// Phase 1: per-block exclusive scan of 1024 contiguous elems (coalesced).
__global__ void scan_p1_kernel() {
    __shared__ int sh[SCAN_B];
    int t = threadIdx.x;
    int i = blockIdx.x * SCAN_B + t;
    int v = (i < N_NODES) ? g_deg[i] : 0;
    sh[t] = v;
    __syncthreads();
    // Hillis-Steele inclusive scan over 1024
    #pragma unroll
    for (int off = 1; off < SCAN_B; off <<= 1) {
        int u = (t >= off) ? sh[t - off] : 0;
        __syncthreads();
        sh[t] += u;
        __syncthreads();
    }
    if (i < N_NODES) g_excl[i] = sh[t] - v;          // exclusive
    if (t == SCAN_B - 1) g_bsum[blockIdx.x] = sh[t]; // block total
}

// Phase 2: exclusive scan of 98 block sums (single small block).
__global__ void scan_p2_kernel() {
    __shared__ int sh[128];
    int t = threadIdx.x;
    int v = (t < SCAN_NBLK) ? g_bsum[t] : 0;
    sh[t] = v;
    __syncthreads();
    #pragma unroll
    for (int off = 1; off < 128; off <<= 1) {
        int u = (t >= off) ? sh[t - off] : 0;
        __syncthreads();
        sh[t] += u;
        __syncthreads();
    }
    if (t < SCAN_NBLK) g_boff[t] = sh[t] - v;        // exclusive
}

// Phase 3: rowptr = local excl + block offset; init cursor; cap rowptr[N].
__global__ void scan_p3_kernel() {
    int i = blockIdx.x * blockDim.x + threadIdx.x;
    if (i < N_NODES) {
        int r = g_excl[i] + g_boff[i / SCAN_B];
        g_rowptr[i] = r;
        g_cursor[i] = r;
    }
    if (i == 0) g_rowptr[N_NODES] = N_EDGES;
}

__global__ void scatter_kernel(const int* __restrict__ src,
                               const int* __restrict__ dst,
                               const float* __restrict__ w) {
    int e = blockIdx.x * blockDim.x + threadIdx.x;
    if (e < N_EDGES) {
        int d   = dst[e];
        int pos = atomicAdd(&g_cursor[d], 1);
        g_csr[pos] = make_int2(src[e], __float_as_int(w[e]));
    }
}

// ---------------- x -> fp16 --------------------------------------------------
__global__ void cvt_kernel(const float* __restrict__ x) {
    int i = blockIdx.x * blockDim.x + threadIdx.x;      // over N*32 half2
    if (i < N_NODES * 32) {
        float2 v = ((const float2*)x)[i];
        g_xh[i] = __float22half2_rn(v);
    }
}

// ---------------- SpMM hop: warp-per-node, fp32 accumulate -------------------
// Uniform-address LDG.64 per edge for {src,w} (L1 broadcast, no shuffles);
// gather is one LDG.32 (half2) per lane per edge = exactly one 128B line/edge.
__device__ __forceinline__ float2
spmm_row(int beg, int end, int lane, const __half2* __restrict__ hin) {
    float2 acc = make_float2(0.0f, 0.0f);
    const int2* __restrict__ csr = g_csr;
    int e = beg;
    for (; e + 4 <= end; e += 4) {
        #pragma unroll
        for (int j = 0; j < 4; j++) {
            int2   sw = __ldg(&csr[e + j]);
            __half2 v = __ldg(hin + ((size_t)sw.x << 5) + lane);
            float  w  = __int_as_float(sw.y);
            float2 vf = __half22float2(v);
            acc.x = fmaf(w, vf.x, acc.x);
            acc.y = fmaf(w, vf.y, acc.y);
        }
    }
    for (; e < end; e++) {
        int2   sw = __ldg(&csr[e]);
        __half2 v = __ldg(hin + ((size_t)sw.x << 5) + lane);
        float  w  = __int_as_float(sw.y);
        float2 vf = __half22float2(v);
        acc.x = fmaf(w, vf.x, acc.x);
        acc.y = fmaf(w, vf.y, acc.y);
    }
    return acc;
}

__global__ void __launch_bounds__(256, 8)
spmm_h2h_kernel(const __half2* __restrict__ hin, __half2* __restrict__ hout) {
    int warp = blockIdx.x * 8 + (threadIdx.x >> 5);
    int lane = threadIdx.x & 31;
    if (warp >= N_NODES) return;
    int beg = g_rowptr[warp], end = g_rowptr[warp + 1];
    float2 acc = spmm_row(beg, end, lane, hin);
    hout[((size_t)warp << 5) + lane] = __float22half2_rn(acc);
}

__global__ void __launch_bounds__(256, 8)
spmm_h2f_kernel(const __half2* __restrict__ hin, float2* __restrict__ hout) {
    int warp = blockIdx.x * 8 + (threadIdx.x >> 5);
    int lane = threadIdx.x & 31;
    if (warp >= N_NODES) return;
    int beg = g_rowptr[warp], end = g_rowptr[warp + 1];
    float2 acc = spmm_row(beg, end, lane, hin);
    hout[((size_t)warp << 5) + lane] = acc;
}

// ---------------- launch -----------------------------------------------------
extern "C" void kernel_launch(void* const* d_in, const int* in_sizes, int n_in,
                              void* d_out, int out_size) {
    const float* x   = (const float*)d_in[0];   // [N, 64]
    const float* ew  = (const float*)d_in[1];   // [E]
    const int*   src = (const int*)d_in[2];     // [E]
    const int*   dst = (const int*)d_in[3];     // [E]
    float* out = (float*)d_out;                 // [N, 64]

    const int TB = 256;
    const int gN  = (N_NODES + TB - 1) / TB;
    const int gE  = (N_EDGES + TB - 1) / TB;
    const int gC  = (N_NODES * 32 + TB - 1) / TB;

    void* degPtr = nullptr;
    cudaGetSymbolAddress(&degPtr, g_deg);
    cudaMemsetAsync(degPtr, 0, N_NODES * sizeof(int));

    // CSR build
    hist_kernel<<<gE, TB>>>(dst);
    scan_p1_kernel<<<SCAN_NBLK, SCAN_B>>>();
    scan_p2_kernel<<<1, 128>>>();
    scan_p3_kernel<<<gN, TB>>>();
    scatter_kernel<<<gE, TB>>>(src, dst, ew);

    // x -> fp16 (independent of CSR chain, same stream anyway)
    cvt_kernel<<<gC, TB>>>(x);

    // 3 hops, warp per node (8 warps per block)
    const int gS = (N_NODES + 7) / 8;

    __half2 *xh = nullptr, *h1 = nullptr, *h2 = nullptr;
    cudaGetSymbolAddress((void**)&xh, g_xh);
    cudaGetSymbolAddress((void**)&h1, g_h1);
    cudaGetSymbolAddress((void**)&h2, g_h2);

    spmm_h2h_kernel<<<gS, TB>>>(xh, h1);
    spmm_h2h_kernel<<<gS, TB>>>(h1, h2);
    spmm_h2f_kernel<<<gS, TB>>>(h2, (float2*)out);
}